// round 10
// baseline (speedup 1.0000x reference)
#include <cuda_runtime.h>

#define NH 192            // nH = nW = 193 - 2 + 1
#define HG 193            // grid H/W
#define MD 64             // vec dim m

// Scratch (allocation-free rule: __device__ globals)
__device__ float g_cosT[NH * MD * MD];   // cos(2*pi*k / T[i,j]),  3 MB
__device__ float g_x[NH * NH * MD];      // x = win_avg(grid) @ M^T, 9.4 MB

// ---- packed f32x2 helpers -------------------------------------------------
__device__ __forceinline__ unsigned long long pk(float x, float y) {
    unsigned long long r;
    asm("mov.b64 %0, {%1, %2};" : "=l"(r) : "f"(x), "f"(y));
    return r;
}
__device__ __forceinline__ float2 upk(unsigned long long v) {
    float2 t;
    asm("mov.b64 {%0, %1}, %2;" : "=f"(t.x), "=f"(t.y) : "l"(v));
    return t;
}
__device__ __forceinline__ unsigned long long fma2(unsigned long long a,
                                                   unsigned long long b,
                                                   unsigned long long c) {
    unsigned long long r;
    asm("fma.rn.f32x2 %0, %1, %2, %3;" : "=l"(r) : "l"(a), "l"(b), "l"(c));
    return r;
}

// ---- cp.async helpers -------------------------------------------------------
__device__ __forceinline__ void cp_async16(unsigned dst_smem, const void* src) {
    asm volatile("cp.async.cg.shared.global [%0], [%1], 16;"
                 :: "r"(dst_smem), "l"(src) : "memory");
}
__device__ __forceinline__ void cp_commit() {
    asm volatile("cp.async.commit_group;" ::: "memory");
}
template <int N>
__device__ __forceinline__ void cp_wait() {
    asm volatile("cp.async.wait_group %0;" :: "n"(N) : "memory");
}

// ---------------------------------------------------------------------------
// Kernel 1: cos table (float4 per thread).  cosT[k,i,j] = cosf(2*pi*k/(i*64+j+2))
// ---------------------------------------------------------------------------
__global__ void __launch_bounds__(512) build_cos_table() {
    int f4 = blockIdx.x * 512 + threadIdx.x;     // 0..196607
    int e  = f4 * 4;
    int k  = e >> 12;
    int r  = e & 4095;
    int i  = r >> 6;
    int jb = r & 63;
    const float TWO_PI = 6.2831853071795864769f;
    float fk = (float)k;
    float4 v;
    v.x = cosf(TWO_PI * fk / (float)(i * MD + jb + 2));
    v.y = cosf(TWO_PI * fk / (float)(i * MD + jb + 3));
    v.z = cosf(TWO_PI * fk / (float)(i * MD + jb + 4));
    v.w = cosf(TWO_PI * fk / (float)(i * MD + jb + 5));
    reinterpret_cast<float4*>(g_cosT)[f4] = v;
}

// ---------------------------------------------------------------------------
// Kernel 2: x[b, j] = sum_l wavg[b, l] * M[j, l]   (R9 version — proven)
// ---------------------------------------------------------------------------
__global__ void __launch_bounds__(256) x_prep(const float* __restrict__ grid,
                                              const float* __restrict__ Mw) {
    __shared__ __align__(16) float sbuf[66 * 64];

    int t  = threadIdx.x;
    int q  = t >> 6;
    int jl = t & 63;

    int bid    = blockIdx.x;
    int k1     = bid / 6;
    int k2base = (bid % 6) * 32;

    for (int e = t; e < 4096; e += 256) sbuf[(e >> 6) * 66 + (e & 63)] = Mw[e];
    __syncthreads();
    unsigned long long Mp[32];
#pragma unroll
    for (int l = 0; l < 32; l++)
        Mp[l] = pk(sbuf[jl * 66 + 2 * l], sbuf[jl * 66 + 2 * l + 1]);
    __syncthreads();

#pragma unroll
    for (int r = 0; r < 8; r++) {
        int e   = t + 256 * r;
        int row = e >> 6;
        int col = e & 63;
        const float* g00 = grid + ((k1 * HG + k2base + row) * MD) + col;
        sbuf[row * 64 + col] = 0.25f * (g00[0] + g00[MD] +
                                        g00[HG * MD] + g00[HG * MD + MD]);
    }
    __syncthreads();

#pragma unroll
    for (int r = 0; r < 8; r++) {
        int k2r = q + 4 * r;
        const ulonglong2* w2 = reinterpret_cast<const ulonglong2*>(&sbuf[k2r * 64]);
        unsigned long long a0 = 0ULL, a1 = 0ULL;
#pragma unroll
        for (int l = 0; l < 16; l++) {
            ulonglong2 w = w2[l];
            a0 = fma2(Mp[2 * l],     w.x, a0);
            a1 = fma2(Mp[2 * l + 1], w.y, a1);
        }
        float2 f0 = upk(a0), f1 = upk(a1);
        g_x[(k1 * NH + k2base + k2r) * MD + jl] = (f0.x + f0.y) + (f1.x + f1.y);
    }
}

// ---------------------------------------------------------------------------
// Main kernel (Chebyshev, low-register variant):
//   Nk[b,i] = sum_j x[b,j] * P[i,j] * cos1[k1,i,j] * cos2[k2,i,j]
//   d_{k+1} = 2cos(theta)*d_k - d_{k-1},  d_k = P*cos1*cos(k*theta)
//
// 512 threads: jq = t&3 (16 j each), i = (t>>2)&63, k1sub = t>>8 (0..1).
// State per thread: tc[8], dcur[8], ndprev[8]  (24 ull = 48 regs — NO SPILL).
// CTA covers 2 k1 x 64 k2; grid (3, 96) = 288 CTAs = 2 waves.
// x staged in 16-k2 blocks via cp.async double buffer (R9 pattern — proven).
// jq lanes reduced with 2 shfl_xor; jq==0 lane stores.
// ---------------------------------------------------------------------------
__global__ void __launch_bounds__(512, 1) main_kernel(const float* __restrict__ P,
                                                      float* __restrict__ out) {
    __shared__ __align__(16) float xs[2][16][2][64];   // 16 KB

    const unsigned long long SGN = 0x8000000080000000ULL;

    int t      = threadIdx.x;
    int jq     = t & 3;
    int i      = (t >> 2) & 63;
    int k1sub  = t >> 8;                // 0..1
    int k1base = blockIdx.y * 2;
    int k1     = k1base + k1sub;
    int k2s    = blockIdx.x * 64;

    // ---- init: tc = 2*cos(theta) (slice k=1); d at k2s; -d at k2s-1 ----
    unsigned long long tc[8], dcur[8], ndprev[8];
    {
        int ro = (i * MD + jq * 16) >> 2;                 // float4 offset in slice
        const float4* c1r = reinterpret_cast<const float4*>(g_cosT) + (k1 << 10) + ro;
        const float4* t1r = reinterpret_cast<const float4*>(g_cosT) + (1 << 10) + ro;
        const float4* c2a = reinterpret_cast<const float4*>(g_cosT) + (k2s << 10) + ro;
        int k2m = (k2s == 0) ? 1 : (k2s - 1);             // cos(-t) = cos(t)
        const float4* c2b = reinterpret_cast<const float4*>(g_cosT) + (k2m << 10) + ro;
        const float4* pr  = reinterpret_cast<const float4*>(P) + ro;
#pragma unroll
        for (int p = 0; p < 4; p++) {
            float4 c1 = c1r[p];
            float4 pp = pr[p];
            float4 th = t1r[p];
            float4 ca = c2a[p];
            float4 cb = c2b[p];
            float e0 = pp.x * c1.x, e1 = pp.y * c1.y;     // C1 = P*cos1
            float e2 = pp.z * c1.z, e3 = pp.w * c1.w;
            tc[2 * p]     = pk(2.f * th.x, 2.f * th.y);
            tc[2 * p + 1] = pk(2.f * th.z, 2.f * th.w);
            dcur[2 * p]     = pk(e0 * ca.x, e1 * ca.y);
            dcur[2 * p + 1] = pk(e2 * ca.z, e3 * ca.w);
            ndprev[2 * p]     = pk(-e0 * cb.x, -e1 * cb.y);
            ndprev[2 * p + 1] = pk(-e2 * cb.z, -e3 * cb.w);
        }
    }

    unsigned xs_base = (unsigned)__cvta_generic_to_shared(&xs[0][0][0][0]);

    // stage one 16-k2 block: 512 float4s, one cp.async per thread
    auto issue_block = [&](int b) {
        int kb = k2s + b * 16;
        unsigned dbase = xs_base + ((b & 1) ? 8192u : 0u);
        int s  = (t >> 8) & 1;                            // k1 row
        int r  = (t >> 4) & 15;                           // k2 offset
        int j4 = t & 15;
        const float4* src = reinterpret_cast<const float4*>(g_x) +
                            (((k1base + s) * NH + kb + r) << 4) + j4;
        unsigned dst = dbase + ((((r * 2 + s) * 64) + j4 * 4) << 2);
        cp_async16(dst, src);
        cp_commit();
    };

    issue_block(0);
    issue_block(1);

    // ---- main loop: 4 blocks x 16 k2 ----
    for (int b = 0; b < 4; b++) {
        if (b >= 1) {
            __syncthreads();            // readers of buf[(b+1)&1] (block b-1) done
            if (b + 1 < 4) issue_block(b + 1);
        }
        if (b + 1 < 4) cp_wait<1>(); else cp_wait<0>();
        __syncthreads();                // block b visible to all

        const float* xbase = &xs[b & 1][0][k1sub][jq * 16];

#pragma unroll 4
        for (int r = 0; r < 16; r++) {
            const ulonglong2* xr =
                reinterpret_cast<const ulonglong2*>(xbase + r * 128);
            unsigned long long a0 = 0ULL, a1 = 0ULL;
#pragma unroll
            for (int p = 0; p < 4; p++) {
                ulonglong2 xv = xr[p];
                a0 = fma2(dcur[2 * p],     xv.x, a0);
                a1 = fma2(dcur[2 * p + 1], xv.y, a1);
            }
            // Chebyshev step (neg via ALU-pipe XOR — overlaps FMA pipe)
#pragma unroll
            for (int p = 0; p < 8; p++) {
                unsigned long long dn = fma2(tc[p], dcur[p], ndprev[p]);
                ndprev[p] = dcur[p] ^ SGN;
                dcur[p]   = dn;
            }
            float2 f0 = upk(a0), f1 = upk(a1);
            float part = (f0.x + f0.y) + (f1.x + f1.y);
            part += __shfl_xor_sync(0xFFFFFFFFu, part, 1);
            part += __shfl_xor_sync(0xFFFFFFFFu, part, 2);
            if (jq == 0) {
                int k2 = k2s + b * 16 + r;
                out[(k1 * NH + k2) * MD + i] = part;
            }
        }
    }
}

// ---------------------------------------------------------------------------
// Launch: inputs in metadata order: grid [193,193,64], M_weight [64,64], P [64,64]
// ---------------------------------------------------------------------------
extern "C" void kernel_launch(void* const* d_in, const int* in_sizes, int n_in,
                              void* d_out, int out_size) {
    const float* grid = (const float*)d_in[0];
    const float* Mw   = (const float*)d_in[1];
    const float* P    = (const float*)d_in[2];
    float* out        = (float*)d_out;

    build_cos_table<<<384, 512>>>();
    x_prep<<<1152, 256>>>(grid, Mw);
    main_kernel<<<dim3(3, 96), 512>>>(P, out);
}